// round 1
// baseline (speedup 1.0000x reference)
#include <cuda_runtime.h>
#include <cuda_bf16.h>
#include <math_constants.h>

#define BB 64
#define SS 4096
#define DD 256
#define CHUNK 32
#define NCHUNK (SS / CHUNK)   // 128

// Scratch (allocation-free: __device__ globals)
__device__ float g_pm[BB * NCHUNK];            // chunk max
__device__ float g_pl[BB * NCHUNK];            // chunk exp-sum
__device__ float g_pa[BB * NCHUNK * DD];       // chunk weighted partial accumulators (8 MB)

// ---------------------------------------------------------------------------
// Kernel 1: one block per (b, chunk). 256 threads (8 warps).
//   Phase 1: each warp loads 4 rows (LDG.128 x2 per lane), computes row dot
//            via warp shuffle reduce, stages tile in smem.
//   Phase 2: warp 0 does chunk-local softmax (max, exp, sum) -- 32 values.
//   Phase 3: thread d accumulates acc[d] = sum_s e[s] * x[s][d] from smem.
// ---------------------------------------------------------------------------
__global__ __launch_bounds__(256) void ta_partial_kernel(
    const float* __restrict__ enc,   // [B, S, D]
    const float* __restrict__ Ww,    // [1, D]
    const float* __restrict__ ut)    // [1, 1]
{
    __shared__ float sx[CHUNK][DD];  // 32 KB tile
    __shared__ float ssc[CHUNK];     // scores -> exp weights

    const int blk  = blockIdx.x;
    const int b    = blk >> 7;       // / NCHUNK
    const int c    = blk & (NCHUNK - 1);
    const int tid  = threadIdx.x;
    const int w    = tid >> 5;
    const int lane = tid & 31;

    const float u = ut[0];

    // per-lane weight fragments: d = 4*lane + {0..3} and 128 + 4*lane + {0..3}
    const float4 w0 = reinterpret_cast<const float4*>(Ww)[lane];
    const float4 w1 = reinterpret_cast<const float4*>(Ww)[lane + 32];

    const float* base = enc + ((size_t)b * SS + (size_t)c * CHUNK) * DD;

    // Phase 1: warp 'w' handles rows sl = w, w+8, w+16, w+24
    #pragma unroll
    for (int i = 0; i < 4; i++) {
        const int sl = w + 8 * i;
        const float4* row4 = reinterpret_cast<const float4*>(base + (size_t)sl * DD);
        const float4 a0 = row4[lane];
        const float4 a1 = row4[lane + 32];
        reinterpret_cast<float4*>(&sx[sl][0])[lane]      = a0;
        reinterpret_cast<float4*>(&sx[sl][0])[lane + 32] = a1;

        float p = a0.x * w0.x;
        p = fmaf(a0.y, w0.y, p);
        p = fmaf(a0.z, w0.z, p);
        p = fmaf(a0.w, w0.w, p);
        p = fmaf(a1.x, w1.x, p);
        p = fmaf(a1.y, w1.y, p);
        p = fmaf(a1.z, w1.z, p);
        p = fmaf(a1.w, w1.w, p);

        #pragma unroll
        for (int off = 16; off > 0; off >>= 1)
            p += __shfl_xor_sync(0xffffffffu, p, off);
        if (lane == 0) ssc[sl] = p;
    }
    __syncthreads();

    // Phase 2: warp 0 computes chunk-local softmax numerators (32 values)
    if (w == 0) {
        float v = u * ssc[lane];
        float m = v;
        #pragma unroll
        for (int off = 16; off > 0; off >>= 1)
            m = fmaxf(m, __shfl_xor_sync(0xffffffffu, m, off));
        const float e = __expf(v - m);
        float l = e;
        #pragma unroll
        for (int off = 16; off > 0; off >>= 1)
            l += __shfl_xor_sync(0xffffffffu, l, off);
        ssc[lane] = e;
        if (lane == 0) {
            g_pm[b * NCHUNK + c] = m;
            g_pl[b * NCHUNK + c] = l;
        }
    }
    __syncthreads();

    // Phase 3: weighted accumulate over the chunk (conflict-free smem reads)
    float acc = 0.f;
    #pragma unroll
    for (int s = 0; s < CHUNK; s++)
        acc = fmaf(ssc[s], sx[s][tid], acc);

    g_pa[((size_t)(b * NCHUNK + c)) * DD + tid] = acc;
}

// ---------------------------------------------------------------------------
// Kernel 2: one block per batch b. Combine NCHUNK partials:
//   M = max_c m_c ; L = sum_c exp(m_c - M) * l_c
//   out[d, b] = (sum_c exp(m_c - M) * acc_c[d]) / L
// ---------------------------------------------------------------------------
__global__ __launch_bounds__(256) void ta_combine_kernel(float* __restrict__ out)
{
    __shared__ float red[256];
    __shared__ float wsc[NCHUNK];

    const int b = blockIdx.x;
    const int t = threadIdx.x;

    // block max over NCHUNK chunk maxima
    float m = (t < NCHUNK) ? g_pm[b * NCHUNK + t] : -CUDART_INF_F;
    red[t] = m;
    __syncthreads();
    #pragma unroll
    for (int off = 128; off > 0; off >>= 1) {
        if (t < off) red[t] = fmaxf(red[t], red[t + off]);
        __syncthreads();
    }
    const float M = red[0];
    __syncthreads();

    // block sum of exp(m_c - M) * l_c
    float contrib = (t < NCHUNK) ? __expf(g_pm[b * NCHUNK + t] - M) * g_pl[b * NCHUNK + t] : 0.f;
    red[t] = contrib;
    __syncthreads();
    #pragma unroll
    for (int off = 128; off > 0; off >>= 1) {
        if (t < off) red[t] += red[t + off];
        __syncthreads();
    }
    const float L = red[0];
    __syncthreads();

    if (t < NCHUNK)
        wsc[t] = __expf(g_pm[b * NCHUNK + t] - M) / L;
    __syncthreads();

    float o = 0.f;
    #pragma unroll 8
    for (int c = 0; c < NCHUNK; c++)
        o = fmaf(wsc[c], g_pa[((size_t)(b * NCHUNK + c)) * DD + t], o);

    // out is [D, B]
    out[t * BB + b] = o;
}

extern "C" void kernel_launch(void* const* d_in, const int* in_sizes, int n_in,
                              void* d_out, int out_size)
{
    const float* enc = (const float*)d_in[0];   // [B, S, D]
    const float* Ww  = (const float*)d_in[1];   // [1, D]
    // d_in[2] = We_b : scalar bias is softmax-invariant, dropped
    const float* ut  = (const float*)d_in[3];   // [1, 1]
    float* out = (float*)d_out;                 // [D, B]

    ta_partial_kernel<<<BB * NCHUNK, 256>>>(enc, Ww, ut);
    ta_combine_kernel<<<BB, 256>>>(out);
}

// round 2
// speedup vs baseline: 1.1364x; 1.1364x over previous
#include <cuda_runtime.h>
#include <cuda_bf16.h>
#include <math_constants.h>

#define BB 64
#define SS 4096
#define DD 256
#define CHUNK 32
#define NCHUNK (SS / CHUNK)   // 128
#define CGROUPS 8             // combine blocks per batch (each handles 32 d's)

// Scratch (allocation-free: __device__ globals)
__device__ float g_pm[BB * NCHUNK];            // chunk max
__device__ float g_pl[BB * NCHUNK];            // chunk exp-sum
__device__ float g_pa[BB * NCHUNK * DD];       // chunk weighted partial accumulators (8 MB)

// ---------------------------------------------------------------------------
// Kernel 1: one block per (b, chunk). 256 threads (8 warps).
// ---------------------------------------------------------------------------
__global__ __launch_bounds__(256) void ta_partial_kernel(
    const float* __restrict__ enc,   // [B, S, D]
    const float* __restrict__ Ww,    // [1, D]
    const float* __restrict__ ut)    // [1, 1]
{
    __shared__ float sx[CHUNK][DD];  // 32 KB tile
    __shared__ float ssc[CHUNK];     // scores -> exp weights

    const int blk  = blockIdx.x;
    const int b    = blk >> 7;       // / NCHUNK
    const int c    = blk & (NCHUNK - 1);
    const int tid  = threadIdx.x;
    const int w    = tid >> 5;
    const int lane = tid & 31;

    const float u = ut[0];

    // per-lane weight fragments: d = 4*lane + {0..3} and 128 + 4*lane + {0..3}
    const float4 w0 = reinterpret_cast<const float4*>(Ww)[lane];
    const float4 w1 = reinterpret_cast<const float4*>(Ww)[lane + 32];

    const float* base = enc + ((size_t)b * SS + (size_t)c * CHUNK) * DD;

    // Phase 1: warp 'w' handles rows sl = w, w+8, w+16, w+24
    #pragma unroll
    for (int i = 0; i < 4; i++) {
        const int sl = w + 8 * i;
        const float4* row4 = reinterpret_cast<const float4*>(base + (size_t)sl * DD);
        const float4 a0 = row4[lane];
        const float4 a1 = row4[lane + 32];
        reinterpret_cast<float4*>(&sx[sl][0])[lane]      = a0;
        reinterpret_cast<float4*>(&sx[sl][0])[lane + 32] = a1;

        // two independent FMA chains (halve RAW latency), join at the end
        float p = a0.x * w0.x;
        float q = a0.y * w0.y;
        p = fmaf(a0.z, w0.z, p);
        q = fmaf(a0.w, w0.w, q);
        p = fmaf(a1.x, w1.x, p);
        q = fmaf(a1.y, w1.y, q);
        p = fmaf(a1.z, w1.z, p);
        q = fmaf(a1.w, w1.w, q);
        p += q;

        #pragma unroll
        for (int off = 16; off > 0; off >>= 1)
            p += __shfl_xor_sync(0xffffffffu, p, off);
        if (lane == 0) ssc[sl] = p;
    }
    __syncthreads();

    // Phase 2: warp 0 computes chunk-local softmax numerators (32 values)
    if (w == 0) {
        float v = u * ssc[lane];
        float m = v;
        #pragma unroll
        for (int off = 16; off > 0; off >>= 1)
            m = fmaxf(m, __shfl_xor_sync(0xffffffffu, m, off));
        const float e = __expf(v - m);
        float l = e;
        #pragma unroll
        for (int off = 16; off > 0; off >>= 1)
            l += __shfl_xor_sync(0xffffffffu, l, off);
        ssc[lane] = e;
        if (lane == 0) {
            g_pm[b * NCHUNK + c] = m;
            g_pl[b * NCHUNK + c] = l;
        }
    }
    __syncthreads();

    // Phase 3: weighted accumulate over the chunk (conflict-free smem reads)
    float acc = 0.f;
    #pragma unroll
    for (int s = 0; s < CHUNK; s++)
        acc = fmaf(ssc[s], sx[s][tid], acc);

    g_pa[((size_t)(b * NCHUNK + c)) * DD + tid] = acc;
}

// ---------------------------------------------------------------------------
// Kernel 2: grid = BB * CGROUPS. Block (b, g) handles d in [g*32, g*32+32).
//   Every block redundantly computes M, L (1 KB read, L2-resident), then
//   256 threads = 8 chunk-lanes x 32 d-lanes each sum 16 strided partials.
// ---------------------------------------------------------------------------
__global__ __launch_bounds__(256) void ta_combine_kernel(float* __restrict__ out)
{
    __shared__ float red[128];
    __shared__ float wsc[NCHUNK];
    __shared__ float acc2[8][32];

    const int b = blockIdx.x >> 3;
    const int g = blockIdx.x & 7;
    const int t = threadIdx.x;
    const int ci = t >> 5;       // 0..7
    const int dl = t & 31;
    const int d  = g * 32 + dl;

    // --- M = max over 128 chunk maxima ---
    if (t < NCHUNK) red[t] = g_pm[b * NCHUNK + t];
    __syncthreads();
    #pragma unroll
    for (int off = 64; off >= 32; off >>= 1) {
        if (t < off) red[t] = fmaxf(red[t], red[t + off]);
        __syncthreads();
    }
    if (t < 32) {
        float m = red[t];
        #pragma unroll
        for (int off = 16; off > 0; off >>= 1)
            m = fmaxf(m, __shfl_xor_sync(0xffffffffu, m, off));
        if (t == 0) red[0] = m;
    }
    __syncthreads();
    const float M = red[0];
    __syncthreads();

    // --- L = sum exp(m_c - M) * l_c ; stash per-chunk numerator in wsc ---
    if (t < NCHUNK) {
        const float e = __expf(g_pm[b * NCHUNK + t] - M);
        wsc[t] = e;
        red[t] = e * g_pl[b * NCHUNK + t];
    }
    __syncthreads();
    #pragma unroll
    for (int off = 64; off >= 32; off >>= 1) {
        if (t < off) red[t] += red[t + off];
        __syncthreads();
    }
    if (t < 32) {
        float l = red[t];
        #pragma unroll
        for (int off = 16; off > 0; off >>= 1)
            l += __shfl_xor_sync(0xffffffffu, l, off);
        if (t == 0) red[0] = l;
    }
    __syncthreads();
    const float Linv = 1.0f / red[0];

    // --- weighted partial sum: thread (ci, dl) covers chunks ci, ci+8, ... ---
    float acc = 0.f;
    #pragma unroll
    for (int i = 0; i < NCHUNK / 8; i++) {
        const int c = ci + 8 * i;
        acc = fmaf(wsc[c], g_pa[((size_t)(b * NCHUNK + c)) * DD + d], acc);
    }
    acc2[ci][dl] = acc;
    __syncthreads();

    if (ci < 4) acc2[ci][dl] += acc2[ci + 4][dl];
    __syncthreads();
    if (ci < 2) acc2[ci][dl] += acc2[ci + 2][dl];
    __syncthreads();
    if (ci == 0) {
        const float o = (acc2[0][dl] + acc2[1][dl]) * Linv;
        out[d * BB + b] = o;   // out is [D, B]
    }
}

extern "C" void kernel_launch(void* const* d_in, const int* in_sizes, int n_in,
                              void* d_out, int out_size)
{
    const float* enc = (const float*)d_in[0];   // [B, S, D]
    const float* Ww  = (const float*)d_in[1];   // [1, D]
    // d_in[2] = We_b : scalar bias is softmax-invariant, dropped
    const float* ut  = (const float*)d_in[3];   // [1, 1]
    float* out = (float*)d_out;                 // [D, B]

    ta_partial_kernel<<<BB * NCHUNK, 256>>>(enc, Ww, ut);
    ta_combine_kernel<<<BB * CGROUPS, 256>>>(out);
}